// round 9
// baseline (speedup 1.0000x reference)
#include <cuda_runtime.h>
#include <cuda_fp16.h>

// FixedFoveatedSensor: out[b,c,h,w] = sum_s bilinear(img, warp(pos_s)) * det_s / sum_s det_s
// img: (4,3,1024,1024) f32, t: (1,) f32, jitter: (16,256,256,2) f32, out: (4,3,256,256) f32
//
// Two-stage: (1) stream img into a channel-interleaved fp16 buffer, 32B record per
// source pixel (12 channels + 4 pad). (2) gather: warp = 2 px x 16 spp; each corner
// fetches all 12 channels with two LDG.128. x-adjacent source pixels are contiguous
// records (4 per 128B line), cutting L1 gather wavefronts ~5x vs planar fp32.

#define SPP 16
#define SH 256
#define SW 256
#define NBC 12
#define NVALS 13
#define PIX_PER_BLOCK 8
#define BLOCK 128
#define IMG_H 1024
#define IMG_W 1024
#define REC 16                         // halves per record (32 B)

__device__ __half g_img16[(size_t)IMG_H * IMG_W * REC];   // 32 MB staged image

// ---------------- stage: planar fp32 -> interleaved fp16 records ----------------
__global__ __launch_bounds__(256)
void stage_kernel(const float* __restrict__ img)
{
    const int px = blockIdx.x * 256 + threadIdx.x;         // 0 .. 1M-1, coalesced in x
    unsigned u[8];
#pragma unroll
    for (int c = 0; c < 6; c++) {
        const float a = img[(size_t)(2 * c)     * (IMG_H * IMG_W) + px];
        const float b = img[(size_t)(2 * c + 1) * (IMG_H * IMG_W) + px];
        const __half2 h = __floats2half2_rn(a, b);
        u[c] = *reinterpret_cast<const unsigned*>(&h);
    }
    u[6] = 0u; u[7] = 0u;
    uint4* dst = reinterpret_cast<uint4*>(g_img16) + (size_t)px * 2;
    dst[0] = make_uint4(u[0], u[1], u[2], u[3]);
    dst[1] = make_uint4(u[4], u[5], u[6], u[7]);
}

// ---------------- gather ----------------
__global__ __launch_bounds__(BLOCK)
void ffs_kernel(const float* __restrict__ t,
                const float* __restrict__ jitter,
                float* __restrict__ out)
{
    __shared__ float red[BLOCK * NVALS];
    __shared__ float det_s[PIX_PER_BLOCK];

    const int tid  = threadIdx.x;
    const int spp  = tid & 15;
    const int pin  = tid >> 4;
    const int pixel = blockIdx.x * PIX_PER_BLOCK + pin;
    const int h = pixel >> 8;
    const int w = pixel & 255;

    const float tt    = t[0];
    const float s_inv = 1.0f / tanhf(tt);
    const float step  = 2.0f / 256.0f;

    const float2 jit = ((const float2*)jitter)[((size_t)spp * SH + h) * SW + w];
    const float posx = fmaf(jit.x, step, -1.0f + (float)w * step);
    const float posy = fmaf(jit.y, step, -1.0f + (float)h * step);

    const float thx = tanhf(tt * posx);
    const float thy = tanhf(tt * posy);
    const float wrx = thx * s_inv;
    const float wry = thy * s_inv;
    const float ddx = tt * (1.0f - thx * thx) * s_inv;
    const float ddy = tt * (1.0f - thy * thy) * s_inv;
    const float det = ddx * ddy;

    float gx = (wrx + 1.0f) * (0.5f * IMG_W) - 0.5f;
    float gy = (wry + 1.0f) * (0.5f * IMG_H) - 0.5f;
    gx = fminf(fmaxf(gx, 0.0f), (float)(IMG_W - 1));
    gy = fminf(fmaxf(gy, 0.0f), (float)(IMG_H - 1));
    const float x0f = floorf(gx);
    const float y0f = floorf(gy);
    const float fx = gx - x0f;
    const float fy = gy - y0f;
    const int x0 = (int)x0f;
    const int y0 = (int)y0f;
    const int x1 = min(x0 + 1, IMG_W - 1);
    const int y1 = min(y0 + 1, IMG_H - 1);

    const float w11 = fx * fy * det;
    const float w01 = fx * det - w11;
    const float w10 = fy * det - w11;
    const float w00 = det - w01 - w10 - w11;

    const uint4* __restrict__ base = reinterpret_cast<const uint4*>(g_img16);
    const size_t r00 = (size_t)(y0 * IMG_W + x0) * 2;
    const size_t r01 = (size_t)(y0 * IMG_W + x1) * 2;
    const size_t r10 = (size_t)(y1 * IMG_W + x0) * 2;
    const size_t r11 = (size_t)(y1 * IMG_W + x1) * 2;

    float acc[NBC];
#pragma unroll
    for (int j = 0; j < NBC; j++) acc[j] = 0.0f;

    // 4 corners x (2 x LDG.128 -> 12 channels), fp32 accumulate
    {
        const size_t rr[4]  = {r00, r01, r10, r11};
        const float  ww[4]  = {w00, w01, w10, w11};
#pragma unroll
        for (int c = 0; c < 4; c++) {
            const uint4 a = base[rr[c]];
            const uint4 b = base[rr[c] + 1];
            const unsigned uu[6] = {a.x, a.y, a.z, a.w, b.x, b.y};
            const float wc = ww[c];
#pragma unroll
            for (int q = 0; q < 6; q++) {
                const float2 f = __half22float2(*reinterpret_cast<const __half2*>(&uu[q]));
                acc[2 * q]     = fmaf(f.x, wc, acc[2 * q]);
                acc[2 * q + 1] = fmaf(f.y, wc, acc[2 * q + 1]);
            }
        }
    }

#pragma unroll
    for (int j = 0; j < NBC; j++) red[tid * NVALS + j] = acc[j];
    red[tid * NVALS + NBC] = det;
    __syncthreads();

    float sum = 0.0f;
    int p = 0, j = 0;
    if (tid < PIX_PER_BLOCK * NVALS) {
        p = tid / NVALS;
        j = tid - p * NVALS;
        const float* b2 = red + (p * SPP) * NVALS + j;
#pragma unroll
        for (int k = 0; k < SPP; k++) sum += b2[k * NVALS];
        if (j == NBC) det_s[p] = sum;
    }
    __syncthreads();

    if (tid < PIX_PER_BLOCK * NVALS && j < NBC) {
        const int opix = blockIdx.x * PIX_PER_BLOCK + p;
        out[(size_t)j * (SH * SW) + opix] = sum / det_s[p];
    }
}

extern "C" void kernel_launch(void* const* d_in, const int* in_sizes, int n_in,
                              void* d_out, int out_size)
{
    const float* img    = (const float*)d_in[0];
    const float* t      = (const float*)d_in[1];
    const float* jitter = (const float*)d_in[2];
    float* out          = (float*)d_out;

    stage_kernel<<<(IMG_H * IMG_W) / 256, 256>>>(img);
    ffs_kernel<<<(SH * SW) / PIX_PER_BLOCK, BLOCK>>>(t, jitter, out);
}